// round 1
// baseline (speedup 1.0000x reference)
#include <cuda_runtime.h>
#include <cuda_bf16.h>
#include <cstddef>

// Problem constants
#define LQ 4096
#define EM 1024
#define HH 16
#define DD 64
#define CHK 128
#define NCH (LQ / CHK)       // 32
#define E3 (3 * EM)          // 3072
#define STATE (DD * DD + DD) // 4160

// -------------------- device scratch (no allocations allowed) --------------------
__device__ float g_qkv[(size_t)LQ * E3];           // 50.3 MB
__device__ float g_attn[(size_t)LQ * EM];          // 16.8 MB
__device__ float g_csum[(size_t)HH * NCH * STATE]; // per-chunk K'^T V and sum(k')
__device__ float g_cpre[(size_t)HH * NCH * STATE]; // exclusive prefix of the above

__device__ __forceinline__ float elup1(float x) {
    return x > 0.f ? x + 1.f : __expf(x);
}

// ==================== generic tiled SIMT fp32 GEMM: C = A@B + bias ====================
// A: MxK row-major, B: KxN row-major, bias: N, C: MxN. M%128==0, N%128==0, K%16==0.
__global__ __launch_bounds__(256) void gemm_bias_kernel(
    const float* __restrict__ A, const float* __restrict__ Bm,
    const float* __restrict__ bias, float* __restrict__ Cm,
    int M, int N, int K)
{
    constexpr int BM = 128, BN = 128, BK = 16;
    __shared__ float As[BK][BM + 4];  // stored transposed: As[k][m]
    __shared__ float Bs[BK][BN + 4];

    const int tid = threadIdx.x;
    const int bm = blockIdx.y * BM;
    const int bn = blockIdx.x * BN;
    const int tm = (tid >> 4) * 8;   // 16x16 thread grid, 8x8 per thread
    const int tn = (tid & 15) * 8;

    float acc[8][8];
#pragma unroll
    for (int i = 0; i < 8; i++)
#pragma unroll
        for (int j = 0; j < 8; j++) acc[i][j] = 0.f;

    for (int k0 = 0; k0 < K; k0 += BK) {
#pragma unroll
        for (int it = 0; it < 2; it++) {
            int f = tid + it * 256;          // 0..511 float4 slots
            int ar = f >> 2, ac = (f & 3) * 4;
            float4 av = *(const float4*)(A + (size_t)(bm + ar) * K + k0 + ac);
            As[ac + 0][ar] = av.x;
            As[ac + 1][ar] = av.y;
            As[ac + 2][ar] = av.z;
            As[ac + 3][ar] = av.w;
            int br = f >> 5, bc = (f & 31) * 4;
            *(float4*)(&Bs[br][bc]) =
                *(const float4*)(Bm + (size_t)(k0 + br) * N + bn + bc);
        }
        __syncthreads();
#pragma unroll
        for (int kk = 0; kk < BK; kk++) {
            float a[8], b[8];
            *(float4*)(a)     = *(const float4*)(&As[kk][tm]);
            *(float4*)(a + 4) = *(const float4*)(&As[kk][tm + 4]);
            *(float4*)(b)     = *(const float4*)(&Bs[kk][tn]);
            *(float4*)(b + 4) = *(const float4*)(&Bs[kk][tn + 4]);
#pragma unroll
            for (int i = 0; i < 8; i++)
#pragma unroll
                for (int j = 0; j < 8; j++) acc[i][j] += a[i] * b[j];
        }
        __syncthreads();
    }

#pragma unroll
    for (int i = 0; i < 8; i++) {
#pragma unroll
        for (int j = 0; j < 8; j++) acc[i][j] += bias[bn + tn + j];
        float4* dst = (float4*)(Cm + (size_t)(bm + tm + i) * N + bn + tn);
        dst[0] = *(float4*)(&acc[i][0]);
        dst[1] = *(float4*)(&acc[i][4]);
    }
}

// ==================== phase A: per-chunk S = K'^T V (64x64), z = sum k' ====================
__global__ __launch_bounds__(256) void chunk_sum_kernel() {
    extern __shared__ float sm[];
    float* Ks = sm;              // [CHK][DD] (elu+1 applied)
    float* Vs = sm + CHK * DD;   // [CHK][DD]

    const int tid = threadIdx.x;
    const int h = blockIdx.x / NCH;
    const int c = blockIdx.x % NCH;

#pragma unroll
    for (int it = 0; it < 8; it++) {
        int f = tid + it * 256;            // 0..2047 float4 slots
        int r = f >> 4, cc = (f & 15) * 4;
        const float* row = g_qkv + (size_t)(c * CHK + r) * E3 + h * DD;
        float4 k4 = *(const float4*)(row + EM + cc);
        float4 t;
        t.x = elup1(k4.x); t.y = elup1(k4.y); t.z = elup1(k4.z); t.w = elup1(k4.w);
        *(float4*)(&Ks[r * DD + cc]) = t;
        *(float4*)(&Vs[r * DD + cc]) = *(const float4*)(row + 2 * EM + cc);
    }
    __syncthreads();

    float* dstS = g_csum + (size_t)(h * NCH + c) * STATE;

    // register-tiled 4x4 outer-product accumulation over the chunk
    const int d0 = (tid >> 4) * 4, e0 = (tid & 15) * 4;
    float sacc[4][4];
#pragma unroll
    for (int i = 0; i < 4; i++)
#pragma unroll
        for (int j = 0; j < 4; j++) sacc[i][j] = 0.f;

#pragma unroll 4
    for (int i = 0; i < CHK; i++) {
        float kr[4], vr[4];
        *(float4*)kr = *(const float4*)(&Ks[i * DD + d0]);
        *(float4*)vr = *(const float4*)(&Vs[i * DD + e0]);
#pragma unroll
        for (int a = 0; a < 4; a++)
#pragma unroll
            for (int b = 0; b < 4; b++) sacc[a][b] += kr[a] * vr[b];
    }
#pragma unroll
    for (int a = 0; a < 4; a++)
        *(float4*)(&dstS[(d0 + a) * DD + e0]) = *(float4*)(&sacc[a][0]);

    if (tid < DD) {
        float z = 0.f;
#pragma unroll 4
        for (int i = 0; i < CHK; i++) z += Ks[i * DD + tid];
        dstS[DD * DD + tid] = z;
    }
}

// ==================== phase B: exclusive prefix over chunks (per head) ====================
__global__ __launch_bounds__(256) void prefix_kernel() {
    const int h = blockIdx.x;
    for (int e = threadIdx.x; e < STATE; e += 256) {
        float acc = 0.f;
#pragma unroll 4
        for (int c = 0; c < NCH; c++) {
            size_t idx = (size_t)(h * NCH + c) * STATE + e;
            g_cpre[idx] = acc;
            acc += g_csum[idx];
        }
    }
}

// ==================== phase C: per-chunk causal attention + inter-chunk state ====================
__global__ __launch_bounds__(256) void chunk_attn_kernel() {
    extern __shared__ float sm[];
    float* QsT = sm;                    // [DD][CHK]  QsT[d][i] = q'(i,d)
    float* KsT = QsT + DD * CHK;        // [DD][CHK]
    float* Vs  = KsT + DD * CHK;        // [CHK][DD]
    float* Sp  = Vs + CHK * DD;         // [DD][DD] exclusive prefix state
    float* ScT = Sp + DD * DD;          // [CHK][CHK]  ScT[j][i] masked scores
    float* zp  = ScT + CHK * CHK;       // [DD]
    float* nrm = zp + DD;               // [CHK] reciprocal norms

    const int tid = threadIdx.x;
    const int h = blockIdx.x / NCH;
    const int c = blockIdx.x % NCH;

    // ---- load & transform ----
#pragma unroll
    for (int it = 0; it < 8; it++) {
        int f = tid + it * 256;
        int r = f >> 4, cc = (f & 15) * 4;
        const float* row = g_qkv + (size_t)(c * CHK + r) * E3 + h * DD;
        float4 q4 = *(const float4*)(row + cc);
        QsT[(cc + 0) * CHK + r] = elup1(q4.x);
        QsT[(cc + 1) * CHK + r] = elup1(q4.y);
        QsT[(cc + 2) * CHK + r] = elup1(q4.z);
        QsT[(cc + 3) * CHK + r] = elup1(q4.w);
        float4 k4 = *(const float4*)(row + EM + cc);
        KsT[(cc + 0) * CHK + r] = elup1(k4.x);
        KsT[(cc + 1) * CHK + r] = elup1(k4.y);
        KsT[(cc + 2) * CHK + r] = elup1(k4.z);
        KsT[(cc + 3) * CHK + r] = elup1(k4.w);
        *(float4*)(&Vs[r * DD + cc]) = *(const float4*)(row + 2 * EM + cc);
    }
    const float* pre = g_cpre + (size_t)(h * NCH + c) * STATE;
#pragma unroll
    for (int it = 0; it < 4; it++) {
        int f = (tid + it * 256) * 4;
        *(float4*)(&Sp[f]) = *(const float4*)(pre + f);
    }
    if (tid < 16)
        *(float4*)(&zp[tid * 4]) = *(const float4*)(pre + DD * DD + tid * 4);
    __syncthreads();

    // ---- causal scores: s(i,j) = q'(i)·k'(j), j<=i ----
    {
        const int ti = (tid >> 4) * 8, tj = (tid & 15) * 8;
        float acc[8][8];
#pragma unroll
        for (int i = 0; i < 8; i++)
#pragma unroll
            for (int j = 0; j < 8; j++) acc[i][j] = 0.f;
#pragma unroll 2
        for (int d = 0; d < DD; d++) {
            float a[8], b[8];
            *(float4*)(a)     = *(const float4*)(&QsT[d * CHK + ti]);
            *(float4*)(a + 4) = *(const float4*)(&QsT[d * CHK + ti + 4]);
            *(float4*)(b)     = *(const float4*)(&KsT[d * CHK + tj]);
            *(float4*)(b + 4) = *(const float4*)(&KsT[d * CHK + tj + 4]);
#pragma unroll
            for (int i = 0; i < 8; i++)
#pragma unroll
                for (int j = 0; j < 8; j++) acc[i][j] += a[i] * b[j];
        }
#pragma unroll
        for (int i = 0; i < 8; i++)
#pragma unroll
            for (int j = 0; j < 8; j++) {
                int gi = ti + i, gj = tj + j;
                ScT[gj * CHK + gi] = (gj <= gi) ? acc[i][j] : 0.f;
            }
    }
    __syncthreads();

    // ---- norms ----
    if (tid < CHK) {
        const int i = tid;
        float nv = 0.f;
#pragma unroll 4
        for (int d = 0; d < DD; d++) nv += QsT[d * CHK + i] * zp[d];
#pragma unroll 4
        for (int j = 0; j < CHK; j++) nv += ScT[j * CHK + i];
        nrm[i] = 1.f / (nv + 1e-6f);
    }
    __syncthreads();

    // ---- output: out(i,e) = q'(i)·Sp(:,e) + sum_j s(i,j) v(j,e) ----
    {
        const int ti = (tid >> 4) * 8, te = (tid & 15) * 4;
        float acc[8][4];
#pragma unroll
        for (int i = 0; i < 8; i++)
#pragma unroll
            for (int j = 0; j < 4; j++) acc[i][j] = 0.f;
#pragma unroll 2
        for (int d = 0; d < DD; d++) {
            float a[8], s4[4];
            *(float4*)(a)     = *(const float4*)(&QsT[d * CHK + ti]);
            *(float4*)(a + 4) = *(const float4*)(&QsT[d * CHK + ti + 4]);
            *(float4*)(s4)    = *(const float4*)(&Sp[d * DD + te]);
#pragma unroll
            for (int i = 0; i < 8; i++)
#pragma unroll
                for (int j = 0; j < 4; j++) acc[i][j] += a[i] * s4[j];
        }
#pragma unroll 2
        for (int j = 0; j < CHK; j++) {
            float a[8], v4[4];
            *(float4*)(a)     = *(const float4*)(&ScT[j * CHK + ti]);
            *(float4*)(a + 4) = *(const float4*)(&ScT[j * CHK + ti + 4]);
            *(float4*)(v4)    = *(const float4*)(&Vs[j * DD + te]);
#pragma unroll
            for (int i = 0; i < 8; i++)
#pragma unroll
                for (int jj = 0; jj < 4; jj++) acc[i][jj] += a[i] * v4[jj];
        }
#pragma unroll
        for (int i = 0; i < 8; i++) {
            float sc = nrm[ti + i];
            float4 o;
            o.x = acc[i][0] * sc;
            o.y = acc[i][1] * sc;
            o.z = acc[i][2] * sc;
            o.w = acc[i][3] * sc;
            *(float4*)(g_attn + (size_t)(c * CHK + ti + i) * EM + h * DD + te) = o;
        }
    }
}

// ==================== launch ====================
extern "C" void kernel_launch(void* const* d_in, const int* in_sizes, int n_in,
                              void* d_out, int out_size) {
    const float* x      = (const float*)d_in[0];
    const float* qkv_w  = (const float*)d_in[1];
    const float* qkv_b  = (const float*)d_in[2];
    const float* out_w  = (const float*)d_in[3];
    const float* out_b  = (const float*)d_in[4];
    float* out = (float*)d_out;

    float *p_qkv = nullptr, *p_attn = nullptr;
    cudaGetSymbolAddress((void**)&p_qkv, g_qkv);
    cudaGetSymbolAddress((void**)&p_attn, g_attn);

    const int SMEM_A = 2 * CHK * DD * (int)sizeof(float);                    // 64 KB
    const int SMEM_C = (2 * DD * CHK + CHK * DD + DD * DD + CHK * CHK + DD + CHK)
                       * (int)sizeof(float);                                 // ~177 KB
    cudaFuncSetAttribute(chunk_sum_kernel,
                         cudaFuncAttributeMaxDynamicSharedMemorySize, SMEM_A);
    cudaFuncSetAttribute(chunk_attn_kernel,
                         cudaFuncAttributeMaxDynamicSharedMemorySize, SMEM_C);

    // 1) QKV projection: (L,E) @ (E,3E) + b
    gemm_bias_kernel<<<dim3(E3 / 128, LQ / 128), 256>>>(x, qkv_w, qkv_b, p_qkv,
                                                        LQ, E3, EM);
    // 2) per-chunk state sums
    chunk_sum_kernel<<<HH * NCH, 256, SMEM_A>>>();
    // 3) exclusive prefix over chunks
    prefix_kernel<<<HH, 256>>>();
    // 4) chunked causal linear attention + normalization
    chunk_attn_kernel<<<HH * NCH, 256, SMEM_C>>>();
    // 5) output projection: (L,E) @ (E,E) + b
    gemm_bias_kernel<<<dim3(EM / 128, LQ / 128), 256>>>(p_attn, out_w, out_b, out,
                                                        LQ, EM, EM);
}

// round 4
// speedup vs baseline: 1.1928x; 1.1928x over previous
#include <cuda_runtime.h>
#include <cuda_bf16.h>
#include <cstdint>
#include <cstddef>

// Problem constants
#define LQ 4096
#define EM 1024
#define HH 16
#define DD 64
#define CHK 128
#define NCH (LQ / CHK)       // 32
#define E3 (3 * EM)          // 3072
#define STATE (DD * DD + DD)

// -------------------- device scratch --------------------
__device__ float g_qkv[(size_t)LQ * E3];
__device__ float g_csum[(size_t)HH * NCH * STATE];
__device__ float g_cpre[(size_t)HH * NCH * STATE];
__device__ __nv_bfloat16 g_xhi[(size_t)LQ * EM];
__device__ __nv_bfloat16 g_xlo[(size_t)LQ * EM];
__device__ __nv_bfloat16 g_wqhi[(size_t)E3 * EM];   // qkv_w^T split [3072][1024]
__device__ __nv_bfloat16 g_wqlo[(size_t)E3 * EM];
__device__ __nv_bfloat16 g_wohi[(size_t)EM * EM];   // out_w^T split [1024][1024]
__device__ __nv_bfloat16 g_wolo[(size_t)EM * EM];
__device__ __nv_bfloat16 g_ahi[(size_t)LQ * EM];    // attention output split
__device__ __nv_bfloat16 g_alo[(size_t)LQ * EM];

__device__ __forceinline__ float elup1(float x) {
    return x > 0.f ? x + 1.f : __expf(x);
}

__device__ __forceinline__ uint32_t smem_u32(const void* p) {
    uint32_t a;
    asm("{ .reg .u64 t; cvta.to.shared.u64 t, %1; cvt.u32.u64 %0, t; }" : "=r"(a) : "l"(p));
    return a;
}

__device__ __forceinline__ void ldsm_x4(uint32_t* r, uint32_t addr) {
    asm volatile("ldmatrix.sync.aligned.m8n8.x4.shared.b16 {%0,%1,%2,%3}, [%4];"
                 : "=r"(r[0]), "=r"(r[1]), "=r"(r[2]), "=r"(r[3]) : "r"(addr));
}

__device__ __forceinline__ void mma_bf16(float* c, const uint32_t* a,
                                         uint32_t b0, uint32_t b1) {
    asm volatile(
        "mma.sync.aligned.m16n8k16.row.col.f32.bf16.bf16.f32 "
        "{%0,%1,%2,%3}, {%4,%5,%6,%7}, {%8,%9}, {%0,%1,%2,%3};"
        : "+f"(c[0]), "+f"(c[1]), "+f"(c[2]), "+f"(c[3])
        : "r"(a[0]), "r"(a[1]), "r"(a[2]), "r"(a[3]), "r"(b0), "r"(b1));
}

// ==================== split kernels ====================
__global__ __launch_bounds__(256) void split_x_kernel(const float* __restrict__ x) {
    size_t i = (size_t)blockIdx.x * 256 + threadIdx.x;
    float v = x[i];
    __nv_bfloat16 hi = __float2bfloat16(v);
    g_xhi[i] = hi;
    g_xlo[i] = __float2bfloat16(v - __bfloat162float(hi));
}

// transpose + split: w[K][N] f32 -> wt_hi/lo [N][K] bf16
__global__ __launch_bounds__(256) void tsplit_kernel(
    const float* __restrict__ w, __nv_bfloat16* __restrict__ thi,
    __nv_bfloat16* __restrict__ tlo, int K, int N)
{
    __shared__ float t[32][33];
    int bx = blockIdx.x * 32;  // N
    int by = blockIdx.y * 32;  // K
    int tx = threadIdx.x & 31, ty = threadIdx.x >> 5;
#pragma unroll
    for (int j = 0; j < 32; j += 8)
        t[ty + j][tx] = w[(size_t)(by + ty + j) * N + bx + tx];
    __syncthreads();
#pragma unroll
    for (int j = 0; j < 32; j += 8) {
        float v = t[tx][ty + j];
        __nv_bfloat16 hi = __float2bfloat16(v);
        size_t o = (size_t)(bx + ty + j) * K + by + tx;
        thi[o] = hi;
        tlo[o] = __float2bfloat16(v - __bfloat162float(hi));
    }
}

// ==================== HMMA bf16x3 GEMM ====================
// C[M][N] = Ahi/lo [M][K] @ (Bhi/lo [N][K])^T + bias, fp32 out.
// CTA 128x128, BK=32, 8 warps (each 64x32), 3-stage cp.async pipeline.
// smem chunk swizzle: 16B chunk c of row r stored at c ^ ((r>>1)&3).
#define SWZOFF(r, c) ((uint32_t)((r) * 64 + (((c) ^ (((r) >> 1) & 3)) << 4)))

__global__ __launch_bounds__(256, 1) void gemm_mma_kernel(
    const __nv_bfloat16* __restrict__ Ahi, const __nv_bfloat16* __restrict__ Alo,
    const __nv_bfloat16* __restrict__ Bhi, const __nv_bfloat16* __restrict__ Blo,
    const float* __restrict__ bias, float* __restrict__ C,
    int M, int N, int K)
{
    extern __shared__ __align__(128) char smem[];   // 3 stages x 32KB
    const uint32_t sbase = smem_u32(smem);
    const int tid = threadIdx.x;
    const int lane = tid & 31;
    const int wid = tid >> 5;
    const int bm = blockIdx.y * 128, bn = blockIdx.x * 128;
    const int wm = (wid >> 2) * 64, wn = (wid & 3) * 32;

    float acc[4][4][4];
#pragma unroll
    for (int i = 0; i < 4; i++)
#pragma unroll
        for (int j = 0; j < 4; j++)
#pragma unroll
            for (int k = 0; k < 4; k++) acc[i][j][k] = 0.f;

    const int nch = K >> 5;

    auto issue = [&](int s, int k0) {
        uint32_t st = sbase + s * 32768;
#pragma unroll
        for (int it = 0; it < 8; ++it) {
            int slot = tid + it * 256;
            int tsel = slot >> 9;                 // 0:Ahi 1:Alo 2:Bhi 3:Blo
            int idx = slot & 511;
            int r = idx >> 2, c = idx & 3;
            const __nv_bfloat16* base =
                tsel == 0 ? Ahi : tsel == 1 ? Alo : tsel == 2 ? Bhi : Blo;
            int row = (tsel < 2 ? bm : bn) + r;
            const void* src = base + (size_t)row * K + k0 + c * 8;
            uint32_t dst = st + tsel * 8192 + SWZOFF(r, c);
            asm volatile("cp.async.cg.shared.global [%0], [%1], 16;"
                         :: "r"(dst), "l"(src) : "memory");
        }
        asm volatile("cp.async.commit_group;" ::: "memory");
    };

    auto compute = [&](int s) {
        uint32_t st = sbase + s * 32768;
#pragma unroll
        for (int ks = 0; ks < 2; ++ks) {
            uint32_t ah[4][4], al[4][4];
#pragma unroll
            for (int mi = 0; mi < 4; ++mi) {
                int r = wm + mi * 16 + (lane & 15);
                int c = 2 * ks + (lane >> 4);
                uint32_t off = SWZOFF(r, c);
                ldsm_x4(ah[mi], st + off);
                ldsm_x4(al[mi], st + 8192 + off);
            }
            uint32_t bh[2][4], bl[2][4];
#pragma unroll
            for (int ng = 0; ng < 2; ++ng) {
                int r = wn + ng * 16 + ((lane >> 4) << 3) + (lane & 7);
                int c = 2 * ks + ((lane >> 3) & 1);
                uint32_t off = SWZOFF(r, c);
                ldsm_x4(bh[ng], st + 16384 + off);
                ldsm_x4(bl[ng], st + 24576 + off);
            }
#pragma unroll
            for (int mi = 0; mi < 4; ++mi)
#pragma unroll
                for (int ni = 0; ni < 4; ++ni) {
                    uint32_t b0 = bh[ni >> 1][(ni & 1) * 2];
                    uint32_t b1 = bh[ni >> 1][(ni & 1) * 2 + 1];
                    uint32_t l0 = bl[ni >> 1][(ni & 1) * 2];
                    uint32_t l1 = bl[ni >> 1][(ni & 1) * 2 + 1];
                    mma_bf16(acc[mi][ni], ah[mi], b0, b1);   // Ahi*Bhi
                    mma_bf16(acc[mi][ni], ah[mi], l0, l1);   // Ahi*Blo
                    mma_bf16(acc[mi][ni], al[mi], b0, b1);   // Alo*Bhi
                }
        }
    };

    // prologue: 2 stages in flight
    issue(0, 0);
    issue(1, 32);

    for (int ch = 0; ch < nch; ++ch) {
        if (ch + 2 < nch) issue((ch + 2) % 3, (ch + 2) << 5);
        else asm volatile("cp.async.commit_group;" ::: "memory");
        asm volatile("cp.async.wait_group 2;" ::: "memory");
        __syncthreads();
        compute(ch % 3);
        __syncthreads();
    }

    // epilogue: direct fused-bias stores (32B-aligned float2 sectors)
#pragma unroll
    for (int mi = 0; mi < 4; ++mi) {
        int row0 = bm + wm + mi * 16 + (lane >> 2);
#pragma unroll
        for (int ni = 0; ni < 4; ++ni) {
            int col = bn + wn + ni * 8 + (lane & 3) * 2;
            float2 b2 = *(const float2*)&bias[col];
            float2 o0 = { acc[mi][ni][0] + b2.x, acc[mi][ni][1] + b2.y };
            float2 o1 = { acc[mi][ni][2] + b2.x, acc[mi][ni][3] + b2.y };
            *(float2*)&C[(size_t)row0 * N + col] = o0;
            *(float2*)&C[(size_t)(row0 + 8) * N + col] = o1;
        }
    }
}

// ==================== phase A: per-chunk S = K'^T V, z = sum k' ====================
__global__ __launch_bounds__(256) void chunk_sum_kernel() {
    extern __shared__ float sm[];
    float* Ks = sm;
    float* Vs = sm + CHK * DD;

    const int tid = threadIdx.x;
    const int h = blockIdx.x / NCH;
    const int c = blockIdx.x % NCH;

#pragma unroll
    for (int it = 0; it < 8; it++) {
        int f = tid + it * 256;
        int r = f >> 4, cc = (f & 15) * 4;
        const float* row = g_qkv + (size_t)(c * CHK + r) * E3 + h * DD;
        float4 k4 = *(const float4*)(row + EM + cc);
        float4 t;
        t.x = elup1(k4.x); t.y = elup1(k4.y); t.z = elup1(k4.z); t.w = elup1(k4.w);
        *(float4*)(&Ks[r * DD + cc]) = t;
        *(float4*)(&Vs[r * DD + cc]) = *(const float4*)(row + 2 * EM + cc);
    }
    __syncthreads();

    float* dstS = g_csum + (size_t)(h * NCH + c) * STATE;
    const int d0 = (tid >> 4) * 4, e0 = (tid & 15) * 4;
    float sacc[4][4];
#pragma unroll
    for (int i = 0; i < 4; i++)
#pragma unroll
        for (int j = 0; j < 4; j++) sacc[i][j] = 0.f;

#pragma unroll 4
    for (int i = 0; i < CHK; i++) {
        float kr[4], vr[4];
        *(float4*)kr = *(const float4*)(&Ks[i * DD + d0]);
        *(float4*)vr = *(const float4*)(&Vs[i * DD + e0]);
#pragma unroll
        for (int a = 0; a < 4; a++)
#pragma unroll
            for (int b = 0; b < 4; b++) sacc[a][b] += kr[a] * vr[b];
    }
#pragma unroll
    for (int a = 0; a < 4; a++)
        *(float4*)(&dstS[(d0 + a) * DD + e0]) = *(float4*)(&sacc[a][0]);

    if (tid < DD) {
        float z = 0.f;
#pragma unroll 4
        for (int i = 0; i < CHK; i++) z += Ks[i * DD + tid];
        dstS[DD * DD + tid] = z;
    }
}

// ==================== phase B: exclusive prefix over chunks ====================
__global__ __launch_bounds__(256) void prefix_kernel() {
    const int h = blockIdx.x;
    for (int e = threadIdx.x; e < STATE; e += 256) {
        float acc = 0.f;
#pragma unroll 4
        for (int c = 0; c < NCH; c++) {
            size_t idx = (size_t)(h * NCH + c) * STATE + e;
            g_cpre[idx] = acc;
            acc += g_csum[idx];
        }
    }
}

// ==================== phase C: chunked causal attention ====================
__global__ __launch_bounds__(256) void chunk_attn_kernel() {
    extern __shared__ float sm[];
    float* QsT = sm;
    float* KsT = QsT + DD * CHK;
    float* Vs  = KsT + DD * CHK;
    float* Sp  = Vs + CHK * DD;
    float* ScT = Sp + DD * DD;
    float* zp  = ScT + CHK * CHK;
    float* nrm = zp + DD;

    const int tid = threadIdx.x;
    const int h = blockIdx.x / NCH;
    const int c = blockIdx.x % NCH;

#pragma unroll
    for (int it = 0; it < 8; it++) {
        int f = tid + it * 256;
        int r = f >> 4, cc = (f & 15) * 4;
        const float* row = g_qkv + (size_t)(c * CHK + r) * E3 + h * DD;
        float4 q4 = *(const float4*)(row + cc);
        QsT[(cc + 0) * CHK + r] = elup1(q4.x);
        QsT[(cc + 1) * CHK + r] = elup1(q4.y);
        QsT[(cc + 2) * CHK + r] = elup1(q4.z);
        QsT[(cc + 3) * CHK + r] = elup1(q4.w);
        float4 k4 = *(const float4*)(row + EM + cc);
        KsT[(cc + 0) * CHK + r] = elup1(k4.x);
        KsT[(cc + 1) * CHK + r] = elup1(k4.y);
        KsT[(cc + 2) * CHK + r] = elup1(k4.z);
        KsT[(cc + 3) * CHK + r] = elup1(k4.w);
        *(float4*)(&Vs[r * DD + cc]) = *(const float4*)(row + 2 * EM + cc);
    }
    const float* pre = g_cpre + (size_t)(h * NCH + c) * STATE;
#pragma unroll
    for (int it = 0; it < 4; it++) {
        int f = (tid + it * 256) * 4;
        *(float4*)(&Sp[f]) = *(const float4*)(pre + f);
    }
    if (tid < 16)
        *(float4*)(&zp[tid * 4]) = *(const float4*)(pre + DD * DD + tid * 4);
    __syncthreads();

    {
        const int ti = (tid >> 4) * 8, tj = (tid & 15) * 8;
        float acc[8][8];
#pragma unroll
        for (int i = 0; i < 8; i++)
#pragma unroll
            for (int j = 0; j < 8; j++) acc[i][j] = 0.f;
#pragma unroll 2
        for (int d = 0; d < DD; d++) {
            float a[8], b[8];
            *(float4*)(a)     = *(const float4*)(&QsT[d * CHK + ti]);
            *(float4*)(a + 4) = *(const float4*)(&QsT[d * CHK + ti + 4]);
            *(float4*)(b)     = *(const float4*)(&KsT[d * CHK + tj]);
            *(float4*)(b + 4) = *(const float4*)(&KsT[d * CHK + tj + 4]);
#pragma unroll
            for (int i = 0; i < 8; i++)
#pragma unroll
                for (int j = 0; j < 8; j++) acc[i][j] += a[i] * b[j];
        }
#pragma unroll
        for (int i = 0; i < 8; i++)
#pragma unroll
            for (int j = 0; j < 8; j++) {
                int gi = ti + i, gj = tj + j;
                ScT[gj * CHK + gi] = (gj <= gi) ? acc[i][j] : 0.f;
            }
    }
    __syncthreads();

    if (tid < CHK) {
        const int i = tid;
        float nv = 0.f;
#pragma unroll 4
        for (int d = 0; d < DD; d++) nv += QsT[d * CHK + i] * zp[d];
#pragma unroll 4
        for (int j = 0; j < CHK; j++) nv += ScT[j * CHK + i];
        nrm[i] = 1.f / (nv + 1e-6f);
    }
    __syncthreads();

    {
        const int ti = (tid >> 4) * 8, te = (tid & 15) * 4;
        float acc[8][4];
#pragma unroll
        for (int i = 0; i < 8; i++)
#pragma unroll
            for (int j = 0; j < 4; j++) acc[i][j] = 0.f;
#pragma unroll 2
        for (int d = 0; d < DD; d++) {
            float a[8], s4[4];
            *(float4*)(a)     = *(const float4*)(&QsT[d * CHK + ti]);
            *(float4*)(a + 4) = *(const float4*)(&QsT[d * CHK + ti + 4]);
            *(float4*)(s4)    = *(const float4*)(&Sp[d * DD + te]);
#pragma unroll
            for (int i = 0; i < 8; i++)
#pragma unroll
                for (int j = 0; j < 4; j++) acc[i][j] += a[i] * s4[j];
        }
#pragma unroll 2
        for (int j = 0; j < CHK; j++) {
            float a[8], v4[4];
            *(float4*)(a)     = *(const float4*)(&ScT[j * CHK + ti]);
            *(float4*)(a + 4) = *(const float4*)(&ScT[j * CHK + ti + 4]);
            *(float4*)(v4)    = *(const float4*)(&Vs[j * DD + te]);
#pragma unroll
            for (int i = 0; i < 8; i++)
#pragma unroll
                for (int jj = 0; jj < 4; jj++) acc[i][jj] += a[i] * v4[jj];
        }
        // write split bf16 (hi/lo) for the tensor-core out-projection
#pragma unroll
        for (int i = 0; i < 8; i++) {
            float sc = nrm[ti + i];
            size_t o = (size_t)(c * CHK + ti + i) * EM + h * DD + te;
            __nv_bfloat16 hi4[4], lo4[4];
#pragma unroll
            for (int jj = 0; jj < 4; jj++) {
                float v = acc[i][jj] * sc;
                __nv_bfloat16 hv = __float2bfloat16(v);
                hi4[jj] = hv;
                lo4[jj] = __float2bfloat16(v - __bfloat162float(hv));
            }
            *(uint2*)(&g_ahi[o]) = *(uint2*)hi4;
            *(uint2*)(&g_alo[o]) = *(uint2*)lo4;
        }
    }
}

// ==================== launch ====================
extern "C" void kernel_launch(void* const* d_in, const int* in_sizes, int n_in,
                              void* d_out, int out_size) {
    const float* x      = (const float*)d_in[0];
    const float* qkv_w  = (const float*)d_in[1];
    const float* qkv_b  = (const float*)d_in[2];
    const float* out_w  = (const float*)d_in[3];
    const float* out_b  = (const float*)d_in[4];
    float* out = (float*)d_out;

    float *p_qkv = nullptr;
    cudaGetSymbolAddress((void**)&p_qkv, g_qkv);
    __nv_bfloat16 *p_xhi, *p_xlo, *p_wqhi, *p_wqlo, *p_wohi, *p_wolo, *p_ahi, *p_alo;
    cudaGetSymbolAddress((void**)&p_xhi, g_xhi);
    cudaGetSymbolAddress((void**)&p_xlo, g_xlo);
    cudaGetSymbolAddress((void**)&p_wqhi, g_wqhi);
    cudaGetSymbolAddress((void**)&p_wqlo, g_wqlo);
    cudaGetSymbolAddress((void**)&p_wohi, g_wohi);
    cudaGetSymbolAddress((void**)&p_wolo, g_wolo);
    cudaGetSymbolAddress((void**)&p_ahi, g_ahi);
    cudaGetSymbolAddress((void**)&p_alo, g_alo);

    const int SMEM_G = 3 * 32768;   // gemm_mma
    const int SMEM_A = 2 * CHK * DD * (int)sizeof(float);
    const int SMEM_C = (2 * DD * CHK + CHK * DD + DD * DD + CHK * CHK + DD + CHK)
                       * (int)sizeof(float);
    cudaFuncSetAttribute(gemm_mma_kernel,
                         cudaFuncAttributeMaxDynamicSharedMemorySize, SMEM_G);
    cudaFuncSetAttribute(chunk_sum_kernel,
                         cudaFuncAttributeMaxDynamicSharedMemorySize, SMEM_A);
    cudaFuncSetAttribute(chunk_attn_kernel,
                         cudaFuncAttributeMaxDynamicSharedMemorySize, SMEM_C);

    // 0) operand preparation (split + transpose-split)
    split_x_kernel<<<(LQ * EM) / 256, 256>>>(x);
    tsplit_kernel<<<dim3(E3 / 32, EM / 32), 256>>>(qkv_w, p_wqhi, p_wqlo, EM, E3);
    tsplit_kernel<<<dim3(EM / 32, EM / 32), 256>>>(out_w, p_wohi, p_wolo, EM, EM);

    // 1) QKV projection (HMMA bf16x3)
    gemm_mma_kernel<<<dim3(E3 / 128, LQ / 128), 256, SMEM_G>>>(
        p_xhi, p_xlo, p_wqhi, p_wqlo, qkv_b, p_qkv, LQ, E3, EM);

    // 2-4) chunked linear attention
    chunk_sum_kernel<<<HH * NCH, 256, SMEM_A>>>();
    prefix_kernel<<<HH, 256>>>();
    chunk_attn_kernel<<<HH * NCH, 256, SMEM_C>>>();

    // 5) output projection (HMMA bf16x3)
    gemm_mma_kernel<<<dim3(EM / 128, LQ / 128), 256, SMEM_G>>>(
        p_ahi, p_alo, p_wohi, p_wolo, out_b, out, LQ, EM, EM);
}

// round 5
// speedup vs baseline: 1.9205x; 1.6101x over previous
#include <cuda_runtime.h>
#include <cuda_bf16.h>
#include <cstdint>
#include <cstddef>

// Problem constants
#define LQ 4096
#define EM 1024
#define HH 16
#define DD 64
#define CHK 128
#define NCH (LQ / CHK)       // 32
#define E3 (3 * EM)          // 3072
#define STATE (DD * DD + DD)

// -------------------- device scratch --------------------
__device__ float g_qkv[(size_t)LQ * E3];
__device__ float g_csum[(size_t)HH * NCH * STATE];
__device__ float g_cpre[(size_t)HH * NCH * STATE];
__device__ __nv_bfloat16 g_xhi[(size_t)LQ * EM];
__device__ __nv_bfloat16 g_xlo[(size_t)LQ * EM];
__device__ __nv_bfloat16 g_wqhi[(size_t)E3 * EM];   // qkv_w^T split [3072][1024]
__device__ __nv_bfloat16 g_wqlo[(size_t)E3 * EM];
__device__ __nv_bfloat16 g_wohi[(size_t)EM * EM];   // out_w^T split [1024][1024]
__device__ __nv_bfloat16 g_wolo[(size_t)EM * EM];
__device__ __nv_bfloat16 g_ahi[(size_t)LQ * EM];    // attention output split
__device__ __nv_bfloat16 g_alo[(size_t)LQ * EM];

__device__ __forceinline__ float elup1(float x) {
    return x > 0.f ? x + 1.f : __expf(x);
}

__device__ __forceinline__ uint32_t smem_u32(const void* p) {
    uint32_t a;
    asm("{ .reg .u64 t; cvta.to.shared.u64 t, %1; cvt.u32.u64 %0, t; }" : "=r"(a) : "l"(p));
    return a;
}

__device__ __forceinline__ void ldsm_x4(uint32_t* r, uint32_t addr) {
    asm volatile("ldmatrix.sync.aligned.m8n8.x4.shared.b16 {%0,%1,%2,%3}, [%4];"
                 : "=r"(r[0]), "=r"(r[1]), "=r"(r[2]), "=r"(r[3]) : "r"(addr));
}

__device__ __forceinline__ void mma_bf16(float* c, const uint32_t* a,
                                         uint32_t b0, uint32_t b1) {
    asm volatile(
        "mma.sync.aligned.m16n8k16.row.col.f32.bf16.bf16.f32 "
        "{%0,%1,%2,%3}, {%4,%5,%6,%7}, {%8,%9}, {%0,%1,%2,%3};"
        : "+f"(c[0]), "+f"(c[1]), "+f"(c[2]), "+f"(c[3])
        : "r"(a[0]), "r"(a[1]), "r"(a[2]), "r"(a[3]), "r"(b0), "r"(b1));
}

// ==================== split kernels ====================
__global__ __launch_bounds__(256) void split_x_kernel(const float* __restrict__ x) {
    size_t i = (size_t)blockIdx.x * 256 + threadIdx.x;
    float v = x[i];
    __nv_bfloat16 hi = __float2bfloat16(v);
    g_xhi[i] = hi;
    g_xlo[i] = __float2bfloat16(v - __bfloat162float(hi));
}

// transpose + split: w[K][N] f32 -> wt_hi/lo [N][K] bf16
__global__ __launch_bounds__(256) void tsplit_kernel(
    const float* __restrict__ w, __nv_bfloat16* __restrict__ thi,
    __nv_bfloat16* __restrict__ tlo, int K, int N)
{
    __shared__ float t[32][33];
    int bx = blockIdx.x * 32;  // N
    int by = blockIdx.y * 32;  // K
    int tx = threadIdx.x & 31, ty = threadIdx.x >> 5;
#pragma unroll
    for (int j = 0; j < 32; j += 8)
        t[ty + j][tx] = w[(size_t)(by + ty + j) * N + bx + tx];
    __syncthreads();
#pragma unroll
    for (int j = 0; j < 32; j += 8) {
        float v = t[tx][ty + j];
        __nv_bfloat16 hi = __float2bfloat16(v);
        size_t o = (size_t)(bx + ty + j) * K + by + tx;
        thi[o] = hi;
        tlo[o] = __float2bfloat16(v - __bfloat162float(hi));
    }
}

// ==================== HMMA bf16x3 GEMM ====================
// C[M][N] = Ahi/lo [M][K] @ (Bhi/lo [N][K])^T + bias, fp32 out.
// CTA 128x128, BK=64, 16 warps (each 32x32), 3-stage cp.async pipeline,
// ONE __syncthreads per K-chunk.
// smem rows are 128B (64 bf16); 16B chunk c of row r stored at c ^ (r&7).
#define SWZ(r, c) ((uint32_t)((r) * 128 + (((c) ^ ((r) & 7)) << 4)))

__global__ __launch_bounds__(512, 1) void gemm_mma_kernel(
    const __nv_bfloat16* __restrict__ Ahi, const __nv_bfloat16* __restrict__ Alo,
    const __nv_bfloat16* __restrict__ Bhi, const __nv_bfloat16* __restrict__ Blo,
    const float* __restrict__ bias, float* __restrict__ C,
    int M, int N, int K)
{
    extern __shared__ __align__(128) char smem[];   // 3 stages x 64KB
    const uint32_t sbase = smem_u32(smem);
    const int tid = threadIdx.x;
    const int lane = tid & 31;
    const int wid = tid >> 5;
    const int bm = blockIdx.y * 128, bn = blockIdx.x * 128;
    const int wm = (wid >> 2) * 32, wn = (wid & 3) * 32;

    float acc[2][4][4];
#pragma unroll
    for (int i = 0; i < 2; i++)
#pragma unroll
        for (int j = 0; j < 4; j++)
#pragma unroll
            for (int k = 0; k < 4; k++) acc[i][j][k] = 0.f;

    const int nch = K >> 6;   // 64-wide K chunks

    auto issue = [&](int s, int k0) {
        uint32_t st = sbase + s * 65536;
#pragma unroll
        for (int it = 0; it < 8; ++it) {
            int slot = tid + it * 512;            // 0..4095
            int tsel = slot >> 10;                // 0:Ahi 1:Alo 2:Bhi 3:Blo
            int idx = slot & 1023;
            int r = idx >> 3, c = idx & 7;
            const __nv_bfloat16* base =
                tsel == 0 ? Ahi : tsel == 1 ? Alo : tsel == 2 ? Bhi : Blo;
            int row = (tsel < 2 ? bm : bn) + r;
            const void* src = base + (size_t)row * K + k0 + c * 8;
            uint32_t dst = st + tsel * 16384 + SWZ(r, c);
            asm volatile("cp.async.cg.shared.global [%0], [%1], 16;"
                         :: "r"(dst), "l"(src) : "memory");
        }
        asm volatile("cp.async.commit_group;" ::: "memory");
    };

    auto compute = [&](int s) {
        uint32_t st = sbase + s * 65536;
#pragma unroll
        for (int ks = 0; ks < 4; ++ks) {
            uint32_t ah[2][4], al[2][4];
#pragma unroll
            for (int mi = 0; mi < 2; ++mi) {
                int r = wm + mi * 16 + (lane & 15);
                int c = 2 * ks + (lane >> 4);
                uint32_t off = SWZ(r, c);
                ldsm_x4(ah[mi], st + off);
                ldsm_x4(al[mi], st + 16384 + off);
            }
            uint32_t bh[2][4], bl[2][4];
#pragma unroll
            for (int ng = 0; ng < 2; ++ng) {
                int r = wn + ng * 16 + ((lane >> 4) << 3) + (lane & 7);
                int c = 2 * ks + ((lane >> 3) & 1);
                uint32_t off = SWZ(r, c);
                ldsm_x4(bh[ng], st + 32768 + off);
                ldsm_x4(bl[ng], st + 49152 + off);
            }
#pragma unroll
            for (int mi = 0; mi < 2; ++mi)
#pragma unroll
                for (int ni = 0; ni < 4; ++ni) {
                    uint32_t b0 = bh[ni >> 1][(ni & 1) * 2];
                    uint32_t b1 = bh[ni >> 1][(ni & 1) * 2 + 1];
                    uint32_t l0 = bl[ni >> 1][(ni & 1) * 2];
                    uint32_t l1 = bl[ni >> 1][(ni & 1) * 2 + 1];
                    mma_bf16(acc[mi][ni], ah[mi], b0, b1);   // Ahi*Bhi
                    mma_bf16(acc[mi][ni], ah[mi], l0, l1);   // Ahi*Blo
                    mma_bf16(acc[mi][ni], al[mi], b0, b1);   // Alo*Bhi
                }
        }
    };

    // prologue: 2 stages in flight
    issue(0, 0);
    issue(1, 64);

    for (int ch = 0; ch < nch; ++ch) {
        asm volatile("cp.async.wait_group 1;" ::: "memory");
        __syncthreads();
        if (ch + 2 < nch) issue((ch + 2) % 3, (ch + 2) << 6);
        else asm volatile("cp.async.commit_group;" ::: "memory");
        compute(ch % 3);
    }

    // epilogue: direct fused-bias stores (32B-aligned float2 sectors)
#pragma unroll
    for (int mi = 0; mi < 2; ++mi) {
        int row0 = bm + wm + mi * 16 + (lane >> 2);
#pragma unroll
        for (int ni = 0; ni < 4; ++ni) {
            int col = bn + wn + ni * 8 + (lane & 3) * 2;
            float2 b2 = *(const float2*)&bias[col];
            float2 o0 = { acc[mi][ni][0] + b2.x, acc[mi][ni][1] + b2.y };
            float2 o1 = { acc[mi][ni][2] + b2.x, acc[mi][ni][3] + b2.y };
            *(float2*)&C[(size_t)row0 * N + col] = o0;
            *(float2*)&C[(size_t)(row0 + 8) * N + col] = o1;
        }
    }
}

// ==================== phase A: per-chunk S = K'^T V, z = sum k' ====================
__global__ __launch_bounds__(256) void chunk_sum_kernel() {
    extern __shared__ float sm[];
    float* Ks = sm;
    float* Vs = sm + CHK * DD;

    const int tid = threadIdx.x;
    const int h = blockIdx.x / NCH;
    const int c = blockIdx.x % NCH;

#pragma unroll
    for (int it = 0; it < 8; it++) {
        int f = tid + it * 256;
        int r = f >> 4, cc = (f & 15) * 4;
        const float* row = g_qkv + (size_t)(c * CHK + r) * E3 + h * DD;
        float4 k4 = *(const float4*)(row + EM + cc);
        float4 t;
        t.x = elup1(k4.x); t.y = elup1(k4.y); t.z = elup1(k4.z); t.w = elup1(k4.w);
        *(float4*)(&Ks[r * DD + cc]) = t;
        *(float4*)(&Vs[r * DD + cc]) = *(const float4*)(row + 2 * EM + cc);
    }
    __syncthreads();

    float* dstS = g_csum + (size_t)(h * NCH + c) * STATE;
    const int d0 = (tid >> 4) * 4, e0 = (tid & 15) * 4;
    float sacc[4][4];
#pragma unroll
    for (int i = 0; i < 4; i++)
#pragma unroll
        for (int j = 0; j < 4; j++) sacc[i][j] = 0.f;

#pragma unroll 4
    for (int i = 0; i < CHK; i++) {
        float kr[4], vr[4];
        *(float4*)kr = *(const float4*)(&Ks[i * DD + d0]);
        *(float4*)vr = *(const float4*)(&Vs[i * DD + e0]);
#pragma unroll
        for (int a = 0; a < 4; a++)
#pragma unroll
            for (int b = 0; b < 4; b++) sacc[a][b] += kr[a] * vr[b];
    }
#pragma unroll
    for (int a = 0; a < 4; a++)
        *(float4*)(&dstS[(d0 + a) * DD + e0]) = *(float4*)(&sacc[a][0]);

    if (tid < DD) {
        float z = 0.f;
#pragma unroll 4
        for (int i = 0; i < CHK; i++) z += Ks[i * DD + tid];
        dstS[DD * DD + tid] = z;
    }
}

// ==================== phase B: exclusive prefix over chunks ====================
__global__ __launch_bounds__(256) void prefix_kernel() {
    const int h = blockIdx.x;
    for (int e = threadIdx.x; e < STATE; e += 256) {
        float acc = 0.f;
#pragma unroll 4
        for (int c = 0; c < NCH; c++) {
            size_t idx = (size_t)(h * NCH + c) * STATE + e;
            g_cpre[idx] = acc;
            acc += g_csum[idx];
        }
    }
}

// ==================== phase C: chunked causal attention ====================
__global__ __launch_bounds__(256) void chunk_attn_kernel() {
    extern __shared__ float sm[];
    float* QsT = sm;
    float* KsT = QsT + DD * CHK;
    float* Vs  = KsT + DD * CHK;
    float* Sp  = Vs + CHK * DD;
    float* ScT = Sp + DD * DD;
    float* zp  = ScT + CHK * CHK;
    float* nrm = zp + DD;

    const int tid = threadIdx.x;
    const int h = blockIdx.x / NCH;
    const int c = blockIdx.x % NCH;

#pragma unroll
    for (int it = 0; it < 8; it++) {
        int f = tid + it * 256;
        int r = f >> 4, cc = (f & 15) * 4;
        const float* row = g_qkv + (size_t)(c * CHK + r) * E3 + h * DD;
        float4 q4 = *(const float4*)(row + cc);
        QsT[(cc + 0) * CHK + r] = elup1(q4.x);
        QsT[(cc + 1) * CHK + r] = elup1(q4.y);
        QsT[(cc + 2) * CHK + r] = elup1(q4.z);
        QsT[(cc + 3) * CHK + r] = elup1(q4.w);
        float4 k4 = *(const float4*)(row + EM + cc);
        KsT[(cc + 0) * CHK + r] = elup1(k4.x);
        KsT[(cc + 1) * CHK + r] = elup1(k4.y);
        KsT[(cc + 2) * CHK + r] = elup1(k4.z);
        KsT[(cc + 3) * CHK + r] = elup1(k4.w);
        *(float4*)(&Vs[r * DD + cc]) = *(const float4*)(row + 2 * EM + cc);
    }
    const float* pre = g_cpre + (size_t)(h * NCH + c) * STATE;
#pragma unroll
    for (int it = 0; it < 4; it++) {
        int f = (tid + it * 256) * 4;
        *(float4*)(&Sp[f]) = *(const float4*)(pre + f);
    }
    if (tid < 16)
        *(float4*)(&zp[tid * 4]) = *(const float4*)(pre + DD * DD + tid * 4);
    __syncthreads();

    {
        const int ti = (tid >> 4) * 8, tj = (tid & 15) * 8;
        float acc[8][8];
#pragma unroll
        for (int i = 0; i < 8; i++)
#pragma unroll
            for (int j = 0; j < 8; j++) acc[i][j] = 0.f;
#pragma unroll 2
        for (int d = 0; d < DD; d++) {
            float a[8], b[8];
            *(float4*)(a)     = *(const float4*)(&QsT[d * CHK + ti]);
            *(float4*)(a + 4) = *(const float4*)(&QsT[d * CHK + ti + 4]);
            *(float4*)(b)     = *(const float4*)(&KsT[d * CHK + tj]);
            *(float4*)(b + 4) = *(const float4*)(&KsT[d * CHK + tj + 4]);
#pragma unroll
            for (int i = 0; i < 8; i++)
#pragma unroll
                for (int j = 0; j < 8; j++) acc[i][j] += a[i] * b[j];
        }
#pragma unroll
        for (int i = 0; i < 8; i++)
#pragma unroll
            for (int j = 0; j < 8; j++) {
                int gi = ti + i, gj = tj + j;
                ScT[gj * CHK + gi] = (gj <= gi) ? acc[i][j] : 0.f;
            }
    }
    __syncthreads();

    if (tid < CHK) {
        const int i = tid;
        float nv = 0.f;
#pragma unroll 4
        for (int d = 0; d < DD; d++) nv += QsT[d * CHK + i] * zp[d];
#pragma unroll 4
        for (int j = 0; j < CHK; j++) nv += ScT[j * CHK + i];
        nrm[i] = 1.f / (nv + 1e-6f);
    }
    __syncthreads();

    {
        const int ti = (tid >> 4) * 8, te = (tid & 15) * 4;
        float acc[8][4];
#pragma unroll
        for (int i = 0; i < 8; i++)
#pragma unroll
            for (int j = 0; j < 4; j++) acc[i][j] = 0.f;
#pragma unroll 2
        for (int d = 0; d < DD; d++) {
            float a[8], s4[4];
            *(float4*)(a)     = *(const float4*)(&QsT[d * CHK + ti]);
            *(float4*)(a + 4) = *(const float4*)(&QsT[d * CHK + ti + 4]);
            *(float4*)(s4)    = *(const float4*)(&Sp[d * DD + te]);
#pragma unroll
            for (int i = 0; i < 8; i++)
#pragma unroll
                for (int j = 0; j < 4; j++) acc[i][j] += a[i] * s4[j];
        }
#pragma unroll 2
        for (int j = 0; j < CHK; j++) {
            float a[8], v4[4];
            *(float4*)(a)     = *(const float4*)(&ScT[j * CHK + ti]);
            *(float4*)(a + 4) = *(const float4*)(&ScT[j * CHK + ti + 4]);
            *(float4*)(v4)    = *(const float4*)(&Vs[j * DD + te]);
#pragma unroll
            for (int i = 0; i < 8; i++)
#pragma unroll
                for (int jj = 0; jj < 4; jj++) acc[i][jj] += a[i] * v4[jj];
        }
        // write split bf16 (hi/lo) for the tensor-core out-projection
#pragma unroll
        for (int i = 0; i < 8; i++) {
            float sc = nrm[ti + i];
            size_t o = (size_t)(c * CHK + ti + i) * EM + h * DD + te;
            __nv_bfloat16 hi4[4], lo4[4];
#pragma unroll
            for (int jj = 0; jj < 4; jj++) {
                float v = acc[i][jj] * sc;
                __nv_bfloat16 hv = __float2bfloat16(v);
                hi4[jj] = hv;
                lo4[jj] = __float2bfloat16(v - __bfloat162float(hv));
            }
            *(uint2*)(&g_ahi[o]) = *(uint2*)hi4;
            *(uint2*)(&g_alo[o]) = *(uint2*)lo4;
        }
    }
}

// ==================== launch ====================
extern "C" void kernel_launch(void* const* d_in, const int* in_sizes, int n_in,
                              void* d_out, int out_size) {
    const float* x      = (const float*)d_in[0];
    const float* qkv_w  = (const float*)d_in[1];
    const float* qkv_b  = (const float*)d_in[2];
    const float* out_w  = (const float*)d_in[3];
    const float* out_b  = (const float*)d_in[4];
    float* out = (float*)d_out;

    float *p_qkv = nullptr;
    cudaGetSymbolAddress((void**)&p_qkv, g_qkv);
    __nv_bfloat16 *p_xhi, *p_xlo, *p_wqhi, *p_wqlo, *p_wohi, *p_wolo, *p_ahi, *p_alo;
    cudaGetSymbolAddress((void**)&p_xhi, g_xhi);
    cudaGetSymbolAddress((void**)&p_xlo, g_xlo);
    cudaGetSymbolAddress((void**)&p_wqhi, g_wqhi);
    cudaGetSymbolAddress((void**)&p_wqlo, g_wqlo);
    cudaGetSymbolAddress((void**)&p_wohi, g_wohi);
    cudaGetSymbolAddress((void**)&p_wolo, g_wolo);
    cudaGetSymbolAddress((void**)&p_ahi, g_ahi);
    cudaGetSymbolAddress((void**)&p_alo, g_alo);

    const int SMEM_G = 3 * 65536;   // gemm_mma: 192 KB
    const int SMEM_A = 2 * CHK * DD * (int)sizeof(float);
    const int SMEM_C = (2 * DD * CHK + CHK * DD + DD * DD + CHK * CHK + DD + CHK)
                       * (int)sizeof(float);
    cudaFuncSetAttribute(gemm_mma_kernel,
                         cudaFuncAttributeMaxDynamicSharedMemorySize, SMEM_G);
    cudaFuncSetAttribute(chunk_sum_kernel,
                         cudaFuncAttributeMaxDynamicSharedMemorySize, SMEM_A);
    cudaFuncSetAttribute(chunk_attn_kernel,
                         cudaFuncAttributeMaxDynamicSharedMemorySize, SMEM_C);

    // 0) operand preparation (split + transpose-split)
    split_x_kernel<<<(LQ * EM) / 256, 256>>>(x);
    tsplit_kernel<<<dim3(E3 / 32, EM / 32), 256>>>(qkv_w, p_wqhi, p_wqlo, EM, E3);
    tsplit_kernel<<<dim3(EM / 32, EM / 32), 256>>>(out_w, p_wohi, p_wolo, EM, EM);

    // 1) QKV projection (HMMA bf16x3)
    gemm_mma_kernel<<<dim3(E3 / 128, LQ / 128), 512, SMEM_G>>>(
        p_xhi, p_xlo, p_wqhi, p_wqlo, qkv_b, p_qkv, LQ, E3, EM);

    // 2-4) chunked linear attention
    chunk_sum_kernel<<<HH * NCH, 256, SMEM_A>>>();
    prefix_kernel<<<HH, 256>>>();
    chunk_attn_kernel<<<HH * NCH, 256, SMEM_C>>>();

    // 5) output projection (HMMA bf16x3)
    gemm_mma_kernel<<<dim3(EM / 128, LQ / 128), 512, SMEM_G>>>(
        p_ahi, p_alo, p_wohi, p_wolo, out_b, out, LQ, EM, EM);
}